// round 7
// baseline (speedup 1.0000x reference)
#include <cuda_runtime.h>
#include <cuda_bf16.h>
#include <cstdint>

#define Bn 128
#define Qn 200
#define Cn 92
#define NT 256
#define FINF 1e9f

struct Smem {
    float cost[Qn * Qn];   // cost[i*Qn + j]
    float v[Qn];           // column potentials snapshot (old v for transfer pass)
    float v2[Qn];          // transferred potentials
    int   y[Qn];           // y[j] = row matched to column j, -1 free
    int   x[Qn];           // x[i] = col matched to row i,    -1 free
    int   predsm[Qn];      // back-pointers for augment walk (rows)
    int   frees[Qn];       // free-row worklist (swap-remove)
    int   nrem;
    int   tc[Qn];
    float lse[Qn];
    float pb[Qn * 4];
    float tb[Qn * 4];
    uint4 slots[2][8];     // per-warp {key, col, irow, e_bits}, parity-buffered
};

// monotone float<->uint key (order preserved under unsigned compare)
__device__ __forceinline__ unsigned fkey(float f) {
    unsigned b = __float_as_uint(f);
    return (b & 0x80000000u) ? ~b : (b | 0x80000000u);
}
__device__ __forceinline__ float keyf(unsigned k) {
    unsigned b = (k & 0x80000000u) ? (k & 0x7fffffffu) : ~k;
    return __uint_as_float(b);
}
__device__ __forceinline__ void umin4(uint4& a, const uint4& b) {
    if (b.x < a.x || (b.x == a.x && b.y < a.y)) a = b;
}

__global__ __launch_bounds__(NT, 1)
void hungarian_loss_kernel(const float* __restrict__ pred_cat,
                           const float* __restrict__ pred_bbox,
                           const int*   __restrict__ tar_cat,
                           const float* __restrict__ tar_bbox,
                           float* __restrict__ out) {
    extern __shared__ char smem_raw[];
    Smem* sm = reinterpret_cast<Smem*>(smem_raw);

    const int b    = blockIdx.x;
    const int tid  = threadIdx.x;
    const int lane = tid & 31;
    const int wid  = tid >> 5;

    // ---------------- Phase A: stage small tensors + per-row logsumexp ------
    if (tid == 0) sm->nrem = 0;
    for (int i = tid; i < Qn; i += NT) { sm->tc[i] = tar_cat[b * Qn + i]; sm->x[i] = -1; sm->y[i] = -1; }
    for (int i = tid; i < Qn * 4; i += NT) {
        sm->pb[i] = pred_bbox[(size_t)b * Qn * 4 + i];
        sm->tb[i] = tar_bbox[(size_t)b * Qn * 4 + i];
    }
    for (int row = wid; row < Qn; row += (NT / 32)) {
        const float* xr = pred_cat + ((size_t)b * Qn + row) * Cn;
        float m = -FINF;
        for (int c = lane; c < Cn; c += 32) m = fmaxf(m, xr[c]);
        #pragma unroll
        for (int o = 16; o; o >>= 1) m = fmaxf(m, __shfl_xor_sync(0xFFFFFFFFu, m, o));
        float s = 0.f;
        for (int c = lane; c < Cn; c += 32) s += expf(xr[c] - m);
        #pragma unroll
        for (int o = 16; o; o >>= 1) s += __shfl_xor_sync(0xFFFFFFFFu, s, o);
        if (lane == 0) sm->lse[row] = m + logf(s);
    }
    __syncthreads();

    // ---------------- Phase B: cost matrix into smem ------------------------
    for (int idx = tid; idx < Qn * Qn; idx += NT) {
        const int i = idx / Qn;
        const int j = idx - i * Qn;
        const int cls = sm->tc[j];
        const float ce = sm->lse[i] - pred_cat[((size_t)b * Qn + i) * Cn + cls];
        float sl1 = 0.f;
        #pragma unroll
        for (int k = 0; k < 4; k++) {
            const float d  = sm->pb[i * 4 + k] - sm->tb[j * 4 + k];
            const float ad = fabsf(d);
            sl1 += (ad < 1.f) ? 0.5f * d * d : (ad - 0.5f);
        }
        const float mask = (cls != 0) ? 1.f : 0.f;
        sm->cost[idx] = ce + sl1 * mask;
    }
    __syncthreads();

    // ---------------- Phase C1: column reduction + greedy tight match -------
    float v_reg = 0.f;
    int   y_reg = -1;
    float e_reg = 0.f;     // u of matched row = cost[y][tid] - v[tid]
    if (tid < Qn) {
        float mn = FINF; int ia = 0;
        for (int i = 0; i < Qn; i++) {
            const float val = sm->cost[i * Qn + tid];
            if (val < mn) { mn = val; ia = i; }
        }
        v_reg = mn;
        if (atomicCAS(&sm->x[ia], -1, tid) == -1) sm->y[tid] = ia;
    }
    __syncthreads();
    if (tid < Qn) { sm->v[tid] = v_reg; sm->v2[tid] = v_reg; }
    __syncthreads();

    // ---------------- Phase C1b: reduction transfer + free tight claims -----
    if (tid < Qn) {
        const int i  = tid;
        const int j1 = sm->x[i];
        float mn = FINF; int jmin = 0;
        int jj = i;                                  // stagger: conflict-free banks
        for (int step = 0; step < Qn; step++) {
            const float r = sm->cost[i * Qn + jj] - sm->v[jj];
            if (jj != j1 && r < mn) { mn = r; jmin = jj; }
            jj++; if (jj == Qn) jj = 0;
        }
        if (j1 >= 0) {
            sm->v2[j1] = sm->v[j1] - mn;             // unique writer per column
        } else if (sm->y[jmin] == -1) {
            if (atomicCAS(&sm->y[jmin], -1, i) == -1) sm->x[i] = jmin;
        }
    }
    __syncthreads();

    // build free-row list; load column state
    if (tid < Qn) {
        if (sm->x[tid] == -1) {
            const int pos = atomicAdd(&sm->nrem, 1);
            sm->frees[pos] = tid;
        }
        v_reg = sm->v2[tid];
        y_reg = sm->y[tid];
        if (y_reg >= 0) e_reg = sm->cost[y_reg * Qn + tid] - v_reg;
    }
    __syncthreads();

    // ---------------- Phase C2: MULTI-SOURCE SSP augmentation ---------------
    // Free rows have implicit u=0 (feasible: v[j] <= colmin always). Each
    // augment = shortest path from the free-row SET to the free-column SET.
    int t = 0;                                   // slot parity
    int nrem = sm->nrem;
    while (nrem > 0) {
        // multi-source init: d[j] = min over free rows of (c[i][j] - v[j])
        float d    = FINF;
        int   pred = -1;
        bool  todo = (tid < Qn);
        if (todo) {
            for (int fi = 0; fi < nrem; fi++) {
                const int i = sm->frees[fi];                 // broadcast read
                const float r = sm->cost[i * Qn + tid] - v_reg;
                if (r < d) { d = r; pred = i; }
            }
        }

        int   jsel;
        float dfin;
        for (;;) {
            const unsigned key  = todo ? fkey(d) : 0xFFFFFFFFu;
            const unsigned rmin = __reduce_min_sync(0xFFFFFFFFu, key);
            const unsigned ball = __ballot_sync(0xFFFFFFFFu, key == rmin);
            // winner lane writes its slot directly (no cross-lane shuffles)
            const int wlane = (rmin == 0xFFFFFFFFu) ? 0 : (__ffs(ball) - 1);
            if (lane == wlane) {
                sm->slots[t][wid] = make_uint4(
                    rmin,
                    (rmin == 0xFFFFFFFFu) ? 0x7fffffffu : (unsigned)tid,
                    (unsigned)y_reg,
                    __float_as_uint(e_reg));
            }
            __syncthreads();                      // only barrier per pop

            uint4 s0 = sm->slots[t][0], s1 = sm->slots[t][1];
            uint4 s2 = sm->slots[t][2], s3 = sm->slots[t][3];
            uint4 s4 = sm->slots[t][4], s5 = sm->slots[t][5];
            uint4 s6 = sm->slots[t][6], s7 = sm->slots[t][7];
            umin4(s0, s1); umin4(s2, s3); umin4(s4, s5); umin4(s6, s7);
            umin4(s0, s2); umin4(s4, s6); umin4(s0, s4);
            t ^= 1;

            const float delta = keyf(s0.x);
            const int   jstar = (int)s0.y;
            const int   irow  = (int)s0.z;

            if (tid == jstar) todo = false;       // pop j*
            if (irow < 0) { jsel = jstar; dfin = delta; break; }

            const float h = __uint_as_float(s0.w) - delta;   // u[irow] - delta
            if (todo) {
                const float nd = sm->cost[irow * Qn + tid] - v_reg - h;
                if (nd < d) { d = nd; pred = irow; }
            }
        }

        // duals + back-pointers, then serial augment walk
        if (tid < Qn) {
            sm->predsm[tid] = pred;
            if (!todo) v_reg += d - dfin;         // popped columns
        }
        __syncthreads();
        if (tid == 0) {
            int j = jsel, i;
            for (;;) {
                i = sm->predsm[j];
                sm->y[j] = i;
                const int jn = sm->x[i];
                sm->x[i] = j;
                if (jn == -1) break;              // reached a free row
                j = jn;
            }
            // swap-remove matched source row from the frees list
            const int nr = sm->nrem;
            for (int k = 0; k < nr; k++) {
                if (sm->frees[k] == i) { sm->frees[k] = sm->frees[nr - 1]; break; }
            }
            sm->nrem = nr - 1;
        }
        __syncthreads();
        nrem = sm->nrem;
        if (tid < Qn) {                           // refresh cached (y, e)
            y_reg = sm->y[tid];
            if (y_reg >= 0) e_reg = sm->cost[y_reg * Qn + tid] - v_reg;
        }
    }

    // ---------------- Phase D: gather matched costs -------------------------
    for (int j = tid; j < Qn; j += NT) {
        const int row = sm->y[j];
        out[b * Qn + row] = sm->cost[row * Qn + j];
    }
}

extern "C" void kernel_launch(void* const* d_in, const int* in_sizes, int n_in,
                              void* d_out, int out_size) {
    const float* pred_cat  = (const float*)d_in[0];
    const float* pred_bbox = (const float*)d_in[1];
    const int*   tar_cat   = (const int*)d_in[2];
    const float* tar_bbox  = (const float*)d_in[3];
    float* out = (float*)d_out;

    static bool attr_set = false;
    if (!attr_set) {
        cudaFuncSetAttribute(hungarian_loss_kernel,
                             cudaFuncAttributeMaxDynamicSharedMemorySize,
                             (int)sizeof(Smem));
        attr_set = true;
    }
    hungarian_loss_kernel<<<Bn, NT, sizeof(Smem)>>>(
        pred_cat, pred_bbox, tar_cat, tar_bbox, out);
}

// round 9
// speedup vs baseline: 1.3370x; 1.3370x over previous
#include <cuda_runtime.h>
#include <cuda_bf16.h>
#include <cstdint>

#define Bn 128
#define Qn 200
#define Cn 92
#define NT 256
#define KC 7            // ceil(200/32) columns per lane
#define FINF 1e9f

struct Smem {
    float cost[Qn * Qn];   // cost[i*Qn + j]
    float v[Qn];           // column potentials snapshot (for transfer pass)
    float v2[Qn];          // transferred potentials
    int   y[Qn];           // y[j] = row matched to column j, -1 free (master)
    int   x[Qn];           // x[i] = col matched to row i,    -1 free
    int   predsm[Qn];      // back-pointers for augment walk
    int   frees[Qn];       // free-row worklist
    int   nfree;
    int   tc[Qn];
    float lse[Qn];
    float pb[Qn * 4];
    float tb[Qn * 4];
};

// monotone float<->uint key (order preserved under unsigned compare)
__device__ __forceinline__ unsigned fkey(float f) {
    unsigned b = __float_as_uint(f);
    return (b & 0x80000000u) ? ~b : (b | 0x80000000u);
}
__device__ __forceinline__ float keyf(unsigned k) {
    unsigned b = (k & 0x80000000u) ? (k & 0x7fffffffu) : ~k;
    return __uint_as_float(b);
}

__global__ __launch_bounds__(NT, 1)
void hungarian_loss_kernel(const float* __restrict__ pred_cat,
                           const float* __restrict__ pred_bbox,
                           const int*   __restrict__ tar_cat,
                           const float* __restrict__ tar_bbox,
                           float* __restrict__ out) {
    extern __shared__ char smem_raw[];
    Smem* sm = reinterpret_cast<Smem*>(smem_raw);

    const int b    = blockIdx.x;
    const int tid  = threadIdx.x;
    const int lane = tid & 31;
    const int wid  = tid >> 5;

    // ---------------- Phase A: stage small tensors + per-row logsumexp ------
    if (tid == 0) sm->nfree = 0;
    for (int i = tid; i < Qn; i += NT) { sm->tc[i] = tar_cat[b * Qn + i]; sm->x[i] = -1; sm->y[i] = -1; }
    for (int i = tid; i < Qn * 4; i += NT) {
        sm->pb[i] = pred_bbox[(size_t)b * Qn * 4 + i];
        sm->tb[i] = tar_bbox[(size_t)b * Qn * 4 + i];
    }
    for (int row = wid; row < Qn; row += (NT / 32)) {
        const float* xr = pred_cat + ((size_t)b * Qn + row) * Cn;
        float m = -FINF;
        for (int c = lane; c < Cn; c += 32) m = fmaxf(m, xr[c]);
        #pragma unroll
        for (int o = 16; o; o >>= 1) m = fmaxf(m, __shfl_xor_sync(0xFFFFFFFFu, m, o));
        float s = 0.f;
        for (int c = lane; c < Cn; c += 32) s += expf(xr[c] - m);
        #pragma unroll
        for (int o = 16; o; o >>= 1) s += __shfl_xor_sync(0xFFFFFFFFu, s, o);
        if (lane == 0) sm->lse[row] = m + logf(s);
    }
    __syncthreads();

    // ---------------- Phase B: cost matrix into smem ------------------------
    for (int idx = tid; idx < Qn * Qn; idx += NT) {
        const int i = idx / Qn;
        const int j = idx - i * Qn;
        const int cls = sm->tc[j];
        const float ce = sm->lse[i] - pred_cat[((size_t)b * Qn + i) * Cn + cls];
        float sl1 = 0.f;
        #pragma unroll
        for (int k = 0; k < 4; k++) {
            const float d  = sm->pb[i * 4 + k] - sm->tb[j * 4 + k];
            const float ad = fabsf(d);
            sl1 += (ad < 1.f) ? 0.5f * d * d : (ad - 0.5f);
        }
        const float mask = (cls != 0) ? 1.f : 0.f;
        sm->cost[idx] = ce + sl1 * mask;
    }
    __syncthreads();

    // ---------------- Phase C1: column reduction + greedy tight match -------
    if (tid < Qn) {
        float mn = FINF; int ia = 0;
        for (int i = 0; i < Qn; i++) {
            const float val = sm->cost[i * Qn + tid];
            if (val < mn) { mn = val; ia = i; }
        }
        sm->v[tid] = mn; sm->v2[tid] = mn;
        if (atomicCAS(&sm->x[ia], -1, tid) == -1) sm->y[tid] = ia;
    }
    __syncthreads();

    // ---------------- Phase C1b: reduction transfer + free tight claims -----
    if (tid < Qn) {
        const int i  = tid;
        const int j1 = sm->x[i];
        float mn = FINF; int jmin = 0;
        int jj = i;                                  // stagger: conflict-free banks
        for (int step = 0; step < Qn; step++) {
            const float r = sm->cost[i * Qn + jj] - sm->v[jj];
            if (jj != j1 && r < mn) { mn = r; jmin = jj; }
            jj++; if (jj == Qn) jj = 0;
        }
        if (j1 >= 0) {
            sm->v2[j1] = sm->v[j1] - mn;             // unique writer per column
        } else if (sm->y[jmin] == -1) {
            if (atomicCAS(&sm->y[jmin], -1, i) == -1) sm->x[i] = jmin;
        }
    }
    __syncthreads();

    // build free-row list
    if (tid < Qn && sm->x[tid] == -1) {
        const int pos = atomicAdd(&sm->nfree, 1);
        sm->frees[pos] = tid;
    }
    __syncthreads();

    // ---------------- warps 1..7 retire; warp 0 solves ----------------------
    if (wid != 0) return;
    const int nf = sm->nfree;

    // lane-owned column state, all registers: column = k*32 + lane
    unsigned act = 0;
    float v[KC], e[KC], d[KC];
    int   ym[KC], pr[KC];
    #pragma unroll
    for (int k = 0; k < KC; k++) {
        const int col = k * 32 + lane;
        v[k] = 0.f; e[k] = 0.f; ym[k] = -1; pr[k] = -1; d[k] = FINF;
        if (col < Qn) {
            act |= 1u << k;
            v[k]  = sm->v2[col];
            ym[k] = sm->y[col];
            if (ym[k] >= 0) e[k] = sm->cost[ym[k] * Qn + col] - v[k];
        }
    }

    // ---------------- Phase C2: JV shortest-path, warp-synchronous ----------
    for (int fi = 0; fi < nf; fi++) {
        const int f = sm->frees[fi];
        const float* frow = sm->cost + f * Qn;

        unsigned todo = act;
        {
            float c[KC];
            #pragma unroll
            for (int k = 0; k < KC; k++)               // batch 7 independent LDS
                c[k] = frow[(k * 32 + lane) % Qn];
            #pragma unroll
            for (int k = 0; k < KC; k++) {
                if (act & (1u << k)) { d[k] = c[k] - v[k]; pr[k] = f; }
            }
        }

        int   jsel;
        float dfin;
        for (;;) {
            // in-register argmin over this lane's live columns
            float bestv = FINF; int bestk = 0; int besty = -1; float beste = 0.f;
            #pragma unroll
            for (int k = 0; k < KC; k++) {
                if ((todo & (1u << k)) && d[k] < bestv) {
                    bestv = d[k]; bestk = k; besty = ym[k]; beste = e[k];
                }
            }
            const unsigned key  = fkey(bestv);
            const unsigned rmin = __reduce_min_sync(0xFFFFFFFFu, key);
            const unsigned ball = __ballot_sync(0xFFFFFFFFu, key == rmin);
            const int src = __ffs(ball) - 1;
            const int   jstar = __shfl_sync(0xFFFFFFFFu, bestk * 32 + lane, src);
            const int   yw    = __shfl_sync(0xFFFFFFFFu, besty, src);
            const float ew    = __shfl_sync(0xFFFFFFFFu, beste, src);
            if (lane == src) todo &= ~(1u << bestk);          // pop j*
            const float delta = keyf(rmin);

            if (yw < 0) { jsel = jstar; dfin = delta; break; }

            const float h = ew - delta;                       // u[yw] - delta
            const float* crow = sm->cost + yw * Qn;
            float c[KC];
            #pragma unroll
            for (int k = 0; k < KC; k++)               // batch 7 independent LDS
                c[k] = crow[(k * 32 + lane) % Qn];
            #pragma unroll
            for (int k = 0; k < KC; k++) {
                if (todo & (1u << k)) {
                    const float nd = c[k] - v[k] - h;
                    if (nd < d[k]) { d[k] = nd; pr[k] = yw; }
                }
            }
        }

        // dual update on popped columns (registers) + dump back-pointers
        #pragma unroll
        for (int k = 0; k < KC; k++) {
            if (act & (1u << k)) {
                if (!(todo & (1u << k))) v[k] += d[k] - dfin;
                sm->predsm[k * 32 + lane] = pr[k];
            }
        }
        __syncwarp();
        if (lane == 0) {                                      // augment walk
            int j = jsel;
            for (;;) {
                const int i  = sm->predsm[j];
                sm->y[j] = i;
                const int jn = sm->x[i];
                sm->x[i] = j;
                if (i == f) break;
                j = jn;
            }
        }
        __syncwarp();
        #pragma unroll
        for (int k = 0; k < KC; k++) {                        // refresh (y, e)
            const int col = k * 32 + lane;
            if (col < Qn) {
                ym[k] = sm->y[col];
                if (ym[k] >= 0) e[k] = sm->cost[ym[k] * Qn + col] - v[k];
            }
        }
    }

    // ---------------- Phase D: gather matched costs (warp 0) ----------------
    for (int j = lane; j < Qn; j += 32) {
        const int row = sm->y[j];
        out[b * Qn + row] = sm->cost[row * Qn + j];
    }
}

extern "C" void kernel_launch(void* const* d_in, const int* in_sizes, int n_in,
                              void* d_out, int out_size) {
    const float* pred_cat  = (const float*)d_in[0];
    const float* pred_bbox = (const float*)d_in[1];
    const int*   tar_cat   = (const int*)d_in[2];
    const float* tar_bbox  = (const float*)d_in[3];
    float* out = (float*)d_out;

    static bool attr_set = false;
    if (!attr_set) {
        cudaFuncSetAttribute(hungarian_loss_kernel,
                             cudaFuncAttributeMaxDynamicSharedMemorySize,
                             (int)sizeof(Smem));
        attr_set = true;
    }
    hungarian_loss_kernel<<<Bn, NT, sizeof(Smem)>>>(
        pred_cat, pred_bbox, tar_cat, tar_bbox, out);
}

// round 15
// speedup vs baseline: 2.5941x; 1.9402x over previous
#include <cuda_runtime.h>
#include <cuda_bf16.h>
#include <cstdint>

#define Bn 128
#define Qn 200
#define Cn 92
#define NT 256
#define NROUNDS 16
#define FINF 1e9f

struct Smem {
    float cost[Qn * Qn];   // cost[i*Qn + j]
    unsigned long long bbuf[Qn];  // per-column packed bids (fkey(v)<<32 | row)
    float v[Qn];           // column potentials (only ever decreases)
    float tbuf[Qn];        // staged transfer values
    int   y[Qn];           // y[j] = row matched to column j, -1 free
    int   x[Qn];           // x[i] = col matched to row i,    -1 free
    int   predsm[Qn];      // back-pointers for augment walk
    int   frees[Qn];       // free-row worklist
    int   nfree;
    int   tc[Qn];
    float lse[Qn];
    float pb[Qn * 4];
    float tb[Qn * 4];
    uint4 slots[2][8];     // per-warp {key, col, irow, e_bits}, parity-buffered
};

// monotone float<->uint key (order preserved under unsigned compare)
__device__ __forceinline__ unsigned fkey(float f) {
    unsigned b = __float_as_uint(f);
    return (b & 0x80000000u) ? ~b : (b | 0x80000000u);
}
__device__ __forceinline__ float keyf(unsigned k) {
    unsigned b = (k & 0x80000000u) ? (k & 0x7fffffffu) : ~k;
    return __uint_as_float(b);
}
__device__ __forceinline__ void umin4(uint4& a, const uint4& b) {
    if (b.x < a.x || (b.x == a.x && b.y < a.y)) a = b;
}

__global__ __launch_bounds__(NT, 1)
void hungarian_loss_kernel(const float* __restrict__ pred_cat,
                           const float* __restrict__ pred_bbox,
                           const int*   __restrict__ tar_cat,
                           const float* __restrict__ tar_bbox,
                           float* __restrict__ out) {
    extern __shared__ char smem_raw[];
    Smem* sm = reinterpret_cast<Smem*>(smem_raw);

    const int b    = blockIdx.x;
    const int tid  = threadIdx.x;
    const int lane = tid & 31;
    const int wid  = tid >> 5;

    // ---------------- Phase A: stage small tensors + per-row logsumexp ------
    if (tid == 0) sm->nfree = 0;
    for (int i = tid; i < Qn; i += NT) { sm->tc[i] = tar_cat[b * Qn + i]; sm->x[i] = -1; sm->y[i] = -1; }
    for (int i = tid; i < Qn * 4; i += NT) {
        sm->pb[i] = pred_bbox[(size_t)b * Qn * 4 + i];
        sm->tb[i] = tar_bbox[(size_t)b * Qn * 4 + i];
    }
    for (int row = wid; row < Qn; row += (NT / 32)) {
        const float* xr = pred_cat + ((size_t)b * Qn + row) * Cn;
        float m = -FINF;
        for (int c = lane; c < Cn; c += 32) m = fmaxf(m, xr[c]);
        #pragma unroll
        for (int o = 16; o; o >>= 1) m = fmaxf(m, __shfl_xor_sync(0xFFFFFFFFu, m, o));
        float s = 0.f;
        for (int c = lane; c < Cn; c += 32) s += expf(xr[c] - m);
        #pragma unroll
        for (int o = 16; o; o >>= 1) s += __shfl_xor_sync(0xFFFFFFFFu, s, o);
        if (lane == 0) sm->lse[row] = m + logf(s);
    }
    __syncthreads();

    // ---------------- Phase B: cost matrix into smem ------------------------
    for (int idx = tid; idx < Qn * Qn; idx += NT) {
        const int i = idx / Qn;
        const int j = idx - i * Qn;
        const int cls = sm->tc[j];
        const float ce = sm->lse[i] - pred_cat[((size_t)b * Qn + i) * Cn + cls];
        float sl1 = 0.f;
        #pragma unroll
        for (int k = 0; k < 4; k++) {
            const float d  = sm->pb[i * 4 + k] - sm->tb[j * 4 + k];
            const float ad = fabsf(d);
            sl1 += (ad < 1.f) ? 0.5f * d * d : (ad - 0.5f);
        }
        const float mask = (cls != 0) ? 1.f : 0.f;
        sm->cost[idx] = ce + sl1 * mask;
    }
    __syncthreads();

    // ---------------- Phase C1: column reduction + greedy tight match -------
    // v[j] = colmin => all slacks >= 0, matched edges tight with u=0. Feasible.
    if (tid < Qn) {
        float mn = FINF; int ia = 0;
        for (int i = 0; i < Qn; i++) {
            const float val = sm->cost[i * Qn + tid];
            if (val < mn) { mn = val; ia = i; }
        }
        sm->v[tid] = mn;
        if (atomicCAS(&sm->x[ia], -1, tid) == -1) sm->y[tid] = ia;
    }
    __syncthreads();

    // ---------------- Phase C1b: Jacobi auction rounds ----------------------
    // Invariant maintained every round: matched edges tight, duals feasible.
    // All v updates strictly DECREASE v => slacks elsewhere only grow.
    for (int r = 0; r < NROUNDS; r++) {
        if (tid < Qn) { sm->bbuf[tid] = ~0ull; sm->tbuf[tid] = FINF; }
        __syncthreads();

        if (tid < Qn) {                          // thread = ROW i
            const int i  = tid;
            const int xi = sm->x[i];
            float mn1 = FINF, mn2 = FINF; int j1 = 0;
            int jj = i;                          // stagger: conflict-free banks
            for (int s = 0; s < Qn; s++) {
                const float rc = sm->cost[i * Qn + jj] - sm->v[jj];
                if (rc < mn1) { mn2 = mn1; mn1 = rc; j1 = jj; }
                else if (rc < mn2) { mn2 = rc; }
                jj++; if (jj == Qn) jj = 0;
            }
            if (xi >= 0) {                       // transfer: tight at 2nd-best
                const float mne = (j1 == xi) ? mn2 : mn1;
                sm->tbuf[xi] = sm->cost[i * Qn + xi] - mne;   // unique writer
            } else {                             // bid with displacement
                const float bidv = sm->cost[i * Qn + j1] - mn2;
                const unsigned long long pk =
                    ((unsigned long long)fkey(bidv) << 32) | (unsigned)i;
                atomicMin(&sm->bbuf[j1], pk);
            }
        }
        __syncthreads();

        if (tid < Qn) {                          // thread = COLUMN j, apply
            const int j = tid;
            const unsigned long long bid = sm->bbuf[j];
            const float tv   = sm->tbuf[j];
            const int owner  = sm->y[j];
            const bool hasb  = (bid != ~0ull);
            const float bidv = keyf((unsigned)(bid >> 32));
            if (owner >= 0) {
                if (hasb && bidv < tv) {         // displacement
                    sm->x[owner] = -1;           // owners/bidders disjoint sets
                    const int nb = (int)(bid & 0xFFFFFFFFull);
                    sm->y[j] = nb; sm->x[nb] = j; sm->v[j] = bidv;
                } else if (tv < FINF) {
                    sm->v[j] = tv;               // transfer (tv <= v[j])
                }
            } else if (hasb) {
                const int nb = (int)(bid & 0xFFFFFFFFull);
                sm->y[j] = nb; sm->x[nb] = j; sm->v[j] = bidv;
            }
        }
        __syncthreads();
    }

    // build free-row list
    if (tid < Qn && sm->x[tid] == -1) {
        const int pos = atomicAdd(&sm->nfree, 1);
        sm->frees[pos] = tid;
    }
    __syncthreads();
    const int nf = sm->nfree;

    // column-owned state in registers (column = tid)
    float v_reg = 0.f;
    int   y_reg = -1;
    float e_reg = 0.f;     // u of matched row = cost[y][tid] - v[tid]
    if (tid < Qn) {
        v_reg = sm->v[tid];
        y_reg = sm->y[tid];
        if (y_reg >= 0) e_reg = sm->cost[y_reg * Qn + tid] - v_reg;
    }
    __syncthreads();

    // ---------------- Phase C2: JV shortest-path augmentation (R6) ----------
    int t = 0;
    for (int fi = 0; fi < nf; fi++) {
        const int f = sm->frees[fi];

        float d    = FINF;
        int   pred = f;
        bool  todo = (tid < Qn);
        if (todo) d = sm->cost[f * Qn + tid] - v_reg;

        int   jsel;
        float dfin;
        for (;;) {
            const unsigned key  = todo ? fkey(d) : 0xFFFFFFFFu;
            const unsigned rmin = __reduce_min_sync(0xFFFFFFFFu, key);
            const unsigned ball = __ballot_sync(0xFFFFFFFFu, key == rmin);
            const int wlane = (rmin == 0xFFFFFFFFu) ? 0 : (__ffs(ball) - 1);
            if (lane == wlane) {                  // winner writes slot directly
                sm->slots[t][wid] = make_uint4(
                    rmin,
                    (rmin == 0xFFFFFFFFu) ? 0x7fffffffu : (unsigned)tid,
                    (unsigned)y_reg,
                    __float_as_uint(e_reg));
            }
            __syncthreads();                      // only barrier per pop

            uint4 s0 = sm->slots[t][0], s1 = sm->slots[t][1];
            uint4 s2 = sm->slots[t][2], s3 = sm->slots[t][3];
            uint4 s4 = sm->slots[t][4], s5 = sm->slots[t][5];
            uint4 s6 = sm->slots[t][6], s7 = sm->slots[t][7];
            umin4(s0, s1); umin4(s2, s3); umin4(s4, s5); umin4(s6, s7);
            umin4(s0, s2); umin4(s4, s6); umin4(s0, s4);
            t ^= 1;

            const float delta = keyf(s0.x);
            const int   jstar = (int)s0.y;
            const int   irow  = (int)s0.z;

            if (tid == jstar) todo = false;       // pop j*
            if (irow < 0) { jsel = jstar; dfin = delta; break; }

            const float h = __uint_as_float(s0.w) - delta;   // u[irow] - delta
            if (todo) {
                const float nd = sm->cost[irow * Qn + tid] - v_reg - h;
                if (nd < d) { d = nd; pred = irow; }
            }
        }

        if (tid < Qn) {
            sm->predsm[tid] = pred;
            if (!todo) v_reg += d - dfin;         // popped columns
        }
        __syncthreads();
        if (tid == 0) {                           // augment walk
            int j = jsel;
            for (;;) {
                const int i  = sm->predsm[j];
                sm->y[j] = i;
                const int jn = sm->x[i];
                sm->x[i] = j;
                if (i == f) break;
                j = jn;
            }
        }
        __syncthreads();
        if (tid < Qn) {                           // refresh cached (y, e)
            y_reg = sm->y[tid];
            if (y_reg >= 0) e_reg = sm->cost[y_reg * Qn + tid] - v_reg;
        }
    }

    // ---------------- Phase D: gather matched costs -------------------------
    for (int j = tid; j < Qn; j += NT) {
        const int row = sm->y[j];
        out[b * Qn + row] = sm->cost[row * Qn + j];
    }
}

extern "C" void kernel_launch(void* const* d_in, const int* in_sizes, int n_in,
                              void* d_out, int out_size) {
    const float* pred_cat  = (const float*)d_in[0];
    const float* pred_bbox = (const float*)d_in[1];
    const int*   tar_cat   = (const int*)d_in[2];
    const float* tar_bbox  = (const float*)d_in[3];
    float* out = (float*)d_out;

    static bool attr_set = false;
    if (!attr_set) {
        cudaFuncSetAttribute(hungarian_loss_kernel,
                             cudaFuncAttributeMaxDynamicSharedMemorySize,
                             (int)sizeof(Smem));
        attr_set = true;
    }
    hungarian_loss_kernel<<<Bn, NT, sizeof(Smem)>>>(
        pred_cat, pred_bbox, tar_cat, tar_bbox, out);
}